// round 3
// baseline (speedup 1.0000x reference)
#include <cuda_runtime.h>

// ---------------- problem constants ----------------
#define S_LEN  512
#define DIN    5
#define HID    128
#define GATES  512
#define NBLK   128     // recurrence blocks, each owns BPB batch rows
#define BPB    8
#define NG     32      // k-groups (of 4) per 128-wide K
#define NCACHE 24      // k-groups cached in smem (24*8KB = 192KB)
#define NSTR   (NG - NCACHE)   // 8 streamed groups (kh=1 half)

// phase-kernel smem layout (float offsets)
#define OFF_WC  0
#define OFF_HH  (NCACHE*GATES*4)           // 49152 : 2 x [8][128] h double buffer
#define OFF_XA  (OFF_HH + 2*BPB*HID)       // 51200 : [16][256] kh-partial exchange
#define OFF_XB  (OFF_XA + 16*256)          // 55296 : [8*2][128] gate exchange
#define PH_SMEM_FLOATS (OFF_XB + 16*128)   // 56320
#define PH_SMEM_BYTES  (PH_SMEM_FLOATS*4)  // 225280

// K4 gemm smem
#define G_OFF_WS 0                         // 32 groups x 128 cols x 4 floats
#define G_OFF_HS (NG*128*4)                // 16384 : 2 x 1024-float h tile
#define G_SMEM_BYTES ((G_OFF_HS + 2*1024)*4)   // 73728

// ---------------- global scratch (static) ----------------
__device__ __align__(16) float g_P1[NG * GATES * 4];   // packed w_hh0
__device__ __align__(16) float g_P2[NG * GATES * 4];   // packed w_hh1
__device__ __align__(16) float g_P3[NG * GATES * 4];   // packed w_ih1
__device__ __align__(16) float g_h1 [(size_t)NBLK * S_LEN * BPB * HID];          // 268MB
__device__ __align__(16) float g_xg0[(size_t)NBLK * S_LEN * GATES * BPB];        // 1GB
__device__ __align__(16) float g_xg1[(size_t)NBLK * S_LEN * GATES * BPB];        // 1GB

// ---------------- helpers ----------------
typedef unsigned long long u64;
__device__ __forceinline__ void ffma2(u64 &d, u64 a, u64 b) {
    asm("fma.rn.f32x2 %0, %1, %2, %0;" : "+l"(d) : "l"(a), "l"(b));
}
__device__ __forceinline__ float flo(u64 v) { return __uint_as_float((unsigned)v); }
__device__ __forceinline__ float fhi(u64 v) { return __uint_as_float((unsigned)(v >> 32)); }
__device__ __forceinline__ float sigf(float x) {
    return __fdividef(1.0f, 1.0f + __expf(-x));
}
__device__ __forceinline__ float tanhf_fast(float x) {
    float e = __expf(2.0f * x);
    return 1.0f - __fdividef(2.0f, e + 1.0f);
}

// ---------------- K1: pack weights ----------------
// P[g][col][dk] = W[col][4g+dk]
__global__ void pack_kernel(const float* __restrict__ whh0,
                            const float* __restrict__ whh1,
                            const float* __restrict__ wih1) {
    int i = blockIdx.x * blockDim.x + threadIdx.x;
    if (i >= GATES * HID) return;
    int col = i / HID, k = i % HID;
    int g = k >> 2, dk = k & 3;
    size_t o = ((size_t)g * GATES + col) * 4 + dk;
    g_P1[o] = whh0[col * HID + k];
    g_P2[o] = whh1[col * HID + k];
    g_P3[o] = wih1[col * HID + k];
}

// ---------------- K2: xg0 = x @ w_ih0^T + b_ih0 + b_hh0 ----------------
// grid (S_LEN, NBLK), 512 threads (one per col). out layout [blk][t][col][b]
__global__ void xg0_kernel(const float* __restrict__ x,
                           const float* __restrict__ wih0,
                           const float* __restrict__ bih0,
                           const float* __restrict__ bhh0) {
    int t = blockIdx.x, blk = blockIdx.y, col = threadIdx.x;
    float wv[DIN];
#pragma unroll
    for (int d = 0; d < DIN; d++) wv[d] = __ldg(wih0 + col * DIN + d);
    float bias = __ldg(bih0 + col) + __ldg(bhh0 + col);
    float o[BPB];
#pragma unroll
    for (int b = 0; b < BPB; b++) {
        const float* xp = x + ((size_t)(blk * BPB + b) * S_LEN + t) * DIN;
        float s = bias;
#pragma unroll
        for (int d = 0; d < DIN; d++) s = fmaf(__ldg(xp + d), wv[d], s);
        o[b] = s;
    }
    float4* dst = (float4*)(g_xg0 + ((size_t)blk * S_LEN + t) * (GATES * BPB) + col * BPB);
    dst[0] = make_float4(o[0], o[1], o[2], o[3]);
    dst[1] = make_float4(o[4], o[5], o[6], o[7]);
}

// ---------------- K4: xg1 = h1 @ w_ih1^T + b_ih1 + b_hh1 ----------------
// grid (4 colslices, NBLK, 2 t-halves), 256 threads. 3 blocks/SM.
__global__ void __launch_bounds__(256, 3) xg1_gemm(const float* __restrict__ bih1,
                                                   const float* __restrict__ bhh1) {
    extern __shared__ float sm[];
    ulonglong2* WsD = (ulonglong2*)(sm + G_OFF_WS);
    const int tid = threadIdx.x;
    const int cs = blockIdx.x, blk = blockIdx.y;
    const int t0 = blockIdx.z * (S_LEN / 2);
    const int cloc = tid >> 1, bh = tid & 1;
    const int col = cs * 128 + cloc;

    // load weight slice (32 groups x 128 cols)
    {
        const ulonglong2* P3D = (const ulonglong2*)g_P3;
        for (int i = tid; i < NG * 128; i += 256) {
            int g = i >> 7, c = i & 127;
            WsD[i] = __ldg(&P3D[g * GATES + cs * 128 + c]);
        }
    }
    const float bias = __ldg(bih1 + col) + __ldg(bhh1 + col);

    // preload tile t0
    ((float4*)(sm + G_OFF_HS))[tid] =
        __ldg((const float4*)(g_h1 + ((size_t)blk * S_LEN + t0) * (BPB * HID)) + tid);
    __syncthreads();

    int pb = 0;
    for (int tt = 0; tt < S_LEN / 2; tt++) {
        int t = t0 + tt;
        bool has = (tt + 1 < S_LEN / 2);
        float4 pre;
        if (has)
            pre = __ldg((const float4*)(g_h1 + ((size_t)blk * S_LEN + t + 1) * (BPB * HID)) + tid);

        const ulonglong2* HrD = (const ulonglong2*)(sm + G_OFF_HS + pb * 1024);
        u64 acc[4] = {0ull, 0ull, 0ull, 0ull};
#pragma unroll 8
        for (int g = 0; g < NG; g++) {
            ulonglong2 w = WsD[g * 128 + cloc];
#pragma unroll
            for (int r = 0; r < 4; r++) {
                ulonglong2 hv = HrD[(bh * 4 + r) * NG + g];
                ffma2(acc[r], w.x, hv.x);
                ffma2(acc[r], w.y, hv.y);
            }
        }
        float4 o = make_float4(flo(acc[0]) + fhi(acc[0]) + bias,
                               flo(acc[1]) + fhi(acc[1]) + bias,
                               flo(acc[2]) + fhi(acc[2]) + bias,
                               flo(acc[3]) + fhi(acc[3]) + bias);
        *(float4*)(g_xg1 + ((size_t)blk * S_LEN + t) * (GATES * BPB) + col * BPB + bh * 4) = o;

        if (has) ((float4*)(sm + G_OFF_HS + (pb ^ 1) * 1024))[tid] = pre;
        __syncthreads();
        pb ^= 1;
    }
}

// ---------------- K3/K5: recurrent phase (K=128) ----------------
// 512 threads: (j in 128, gp in 2, kh in 2). kh splits K. kh0 finalizes.
template<int PHASE>
__global__ void __launch_bounds__(512, 1) lstm_phase(
    const float* __restrict__ fcw,
    const float* __restrict__ fcb,
    float* __restrict__ out)
{
    extern __shared__ float sm[];
    const float* Pg  = (PHASE == 1) ? g_P1  : g_P2;
    const float* Xg  = (PHASE == 1) ? g_xg0 : g_xg1;

    const int tid = threadIdx.x;
    const int j   = tid & (HID - 1);
    const int gp  = (tid >> 7) & 1;
    const int kh  = tid >> 8;
    const int col0 = 2 * gp * HID + j;
    const int col1 = col0 + HID;
    const int blk  = blockIdx.x;
    const int mb = gp * 4, ob = (gp ^ 1) * 4;

    // load cached weights, zero h buffer 0
    {
        const float4* src = (const float4*)Pg;
        float4*       dst = (float4*)(sm + OFF_WC);
        for (int i = tid; i < NCACHE * GATES; i += 512) dst[i] = __ldg(src + i);
    }
    for (int i = tid; i < 2 * BPB * HID; i += 512) sm[OFF_HH + i] = 0.f;
    __syncthreads();

    const ulonglong2* WcD = (const ulonglong2*)(sm + OFF_WC);
    const ulonglong2* PgD = (const ulonglong2*)Pg;

    float c[4] = {0.f, 0.f, 0.f, 0.f};

    for (int t = 0; t < S_LEN; t++) {
        const int rb = t & 1, wb = rb ^ 1;
        const ulonglong2* HrD = (const ulonglong2*)(sm + OFF_HH + rb * BPB * HID);

        u64 a0[BPB], a1[BPB];
#pragma unroll
        for (int b = 0; b < BPB; b++) { a0[b] = 0ull; a1[b] = 0ull; }

        float4 xa0, xa1, xb0, xb1;   // xg prefetch (kh0 only)

        if (kh == 0) {
            const float4* xp = (const float4*)(Xg + ((size_t)blk * S_LEN + t) * (GATES * BPB));
            xa0 = __ldg(xp + col0 * 2);
            xa1 = __ldg(xp + col0 * 2 + 1);
            xb0 = __ldg(xp + col1 * 2);
            xb1 = __ldg(xp + col1 * 2 + 1);
            // groups 0..15 all cached
#pragma unroll 4
            for (int g = 0; g < 16; g++) {
                ulonglong2 w0 = WcD[g * GATES + col0];
                ulonglong2 w1 = WcD[g * GATES + col1];
#pragma unroll
                for (int b = 0; b < BPB; b++) {
                    ulonglong2 hv = HrD[b * NG + g];
                    ffma2(a0[b], w0.x, hv.x); ffma2(a0[b], w0.y, hv.y);
                    ffma2(a1[b], w1.x, hv.x); ffma2(a1[b], w1.y, hv.y);
                }
            }
        } else {
            // streamed groups 24..31 with rolling 3-deep prefetch
            ulonglong2 wsa[3], wsb[3];
#pragma unroll
            for (int s = 0; s < 3; s++) {
                wsa[s] = __ldg(&PgD[(NCACHE + s) * GATES + col0]);
                wsb[s] = __ldg(&PgD[(NCACHE + s) * GATES + col1]);
            }
#pragma unroll
            for (int s = 0; s < NSTR; s++) {
                int g = NCACHE + s;
                ulonglong2 w0 = wsa[s % 3], w1 = wsb[s % 3];
                if (s + 3 < NSTR) {
                    wsa[s % 3] = __ldg(&PgD[(g + 3) * GATES + col0]);
                    wsb[s % 3] = __ldg(&PgD[(g + 3) * GATES + col1]);
                }
#pragma unroll
                for (int b = 0; b < BPB; b++) {
                    ulonglong2 hv = HrD[b * NG + g];
                    ffma2(a0[b], w0.x, hv.x); ffma2(a0[b], w0.y, hv.y);
                    ffma2(a1[b], w1.x, hv.x); ffma2(a1[b], w1.y, hv.y);
                }
            }
            // cached groups 16..23
#pragma unroll 4
            for (int g = 16; g < NCACHE; g++) {
                ulonglong2 w0 = WcD[g * GATES + col0];
                ulonglong2 w1 = WcD[g * GATES + col1];
#pragma unroll
                for (int b = 0; b < BPB; b++) {
                    ulonglong2 hv = HrD[b * NG + g];
                    ffma2(a0[b], w0.x, hv.x); ffma2(a0[b], w0.y, hv.y);
                    ffma2(a1[b], w1.x, hv.x); ffma2(a1[b], w1.y, hv.y);
                }
            }
        }

        // horizontal reduce
        float s0[BPB], s1[BPB];
#pragma unroll
        for (int b = 0; b < BPB; b++) {
            s0[b] = flo(a0[b]) + fhi(a0[b]);
            s1[b] = flo(a1[b]) + fhi(a1[b]);
        }

        // kh1 exports partials (transposed layout: [q*8+b][gp*128+j], conflict-free)
        if (kh == 1) {
#pragma unroll
            for (int b = 0; b < BPB; b++) {
                sm[OFF_XA + (0 * 8 + b) * 256 + gp * 128 + j] = s0[b];
                sm[OFF_XA + (1 * 8 + b) * 256 + gp * 128 + j] = s1[b];
            }
        }
        __syncthreads();   // #1

        if (kh == 0) {
            float g0[BPB], g1[BPB];
            float xg0v[8] = {xa0.x, xa0.y, xa0.z, xa0.w, xa1.x, xa1.y, xa1.z, xa1.w};
            float xg1v[8] = {xb0.x, xb0.y, xb0.z, xb0.w, xb1.x, xb1.y, xb1.z, xb1.w};
#pragma unroll
            for (int b = 0; b < BPB; b++) {
                g0[b] = s0[b] + sm[OFF_XA + (0 * 8 + b) * 256 + gp * 128 + j] + xg0v[b];
                g1[b] = s1[b] + sm[OFF_XA + (1 * 8 + b) * 256 + gp * 128 + j] + xg1v[b];
            }
            // export other-half gates
#pragma unroll
            for (int r = 0; r < 4; r++) {
                int b = ob + r;
                sm[OFF_XB + (b * 2 + 0) * 128 + j] = g0[b];
                sm[OFF_XB + (b * 2 + 1) * 128 + j] = g1[b];
            }
            __syncthreads();   // #2
            float* Hw = sm + OFF_HH + wb * BPB * HID;
#pragma unroll
            for (int r = 0; r < 4; r++) {
                int b = mb + r;
                float A = sm[OFF_XB + (b * 2 + 0) * 128 + j];
                float B = sm[OFF_XB + (b * 2 + 1) * 128 + j];
                float iv, fv, gv, ov;
                if (gp == 0) { iv = g0[b]; fv = g1[b]; gv = A; ov = B; }
                else         { gv = g0[b]; ov = g1[b]; iv = A; fv = B; }
                c[r] = sigf(fv) * c[r] + sigf(iv) * tanhf_fast(gv);
                float h = sigf(ov) * tanhf_fast(c[r]);
                Hw[b * HID + j] = h;
                if (PHASE == 1)
                    g_h1[((size_t)(blk * S_LEN + t) * BPB + b) * HID + j] = h;
            }
        } else {
            __syncthreads();   // #2
        }
        __syncthreads();       // #3
    }

    if (PHASE == 2) {
        const float* hfin = sm + OFF_HH;   // t=511 wrote buffer 0
        int w = tid >> 5, lane = tid & 31;
        if (w < BPB) {
            float s = 0.f;
#pragma unroll
            for (int m = 0; m < HID; m += 32)
                s += hfin[w * HID + lane + m] * __ldg(fcw + lane + m);
#pragma unroll
            for (int o = 16; o > 0; o >>= 1) s += __shfl_down_sync(0xffffffffu, s, o);
            if (lane == 0) out[blk * BPB + w] = s + __ldg(fcb);
        }
    }
}

// ---------------- launch ----------------
extern "C" void kernel_launch(void* const* d_in, const int* in_sizes, int n_in,
                              void* d_out, int out_size) {
    const float* x    = (const float*)d_in[0];
    const float* wih0 = (const float*)d_in[1];
    const float* whh0 = (const float*)d_in[2];
    const float* bih0 = (const float*)d_in[3];
    const float* bhh0 = (const float*)d_in[4];
    const float* wih1 = (const float*)d_in[5];
    const float* whh1 = (const float*)d_in[6];
    const float* bih1 = (const float*)d_in[7];
    const float* bhh1 = (const float*)d_in[8];
    const float* fcw  = (const float*)d_in[9];
    const float* fcb  = (const float*)d_in[10];
    float* out = (float*)d_out;
    (void)in_sizes; (void)n_in; (void)out_size;

    cudaFuncSetAttribute(lstm_phase<1>, cudaFuncAttributeMaxDynamicSharedMemorySize, PH_SMEM_BYTES);
    cudaFuncSetAttribute(lstm_phase<2>, cudaFuncAttributeMaxDynamicSharedMemorySize, PH_SMEM_BYTES);
    cudaFuncSetAttribute(xg1_gemm,      cudaFuncAttributeMaxDynamicSharedMemorySize, G_SMEM_BYTES);

    pack_kernel<<<(GATES * HID + 255) / 256, 256>>>(whh0, whh1, wih1);
    xg0_kernel<<<dim3(S_LEN, NBLK), GATES>>>(x, wih0, bih0, bhh0);
    lstm_phase<1><<<NBLK, 512, PH_SMEM_BYTES>>>(fcw, fcb, out);
    xg1_gemm<<<dim3(4, NBLK, 2), 256, G_SMEM_BYTES>>>(bih1, bhh1);
    lstm_phase<2><<<NBLK, 512, PH_SMEM_BYTES>>>(fcw, fcb, out);
}

// round 4
// speedup vs baseline: 1.1690x; 1.1690x over previous
#include <cuda_runtime.h>

// ---------------- problem constants ----------------
#define S_LEN  512
#define DIN    5
#define HID    128
#define GATES  512
#define NBLK   128     // recurrence blocks, each owns BPB batch rows
#define BPB    8
#define NG     32      // k-groups (of 4) per 128-wide K
#define NCACHE 21      // k-groups cached in smem
#define NTH    768     // phase kernel threads

// phase-kernel smem layout (float offsets)
#define OFF_WC  0
#define OFF_HH  (NCACHE*GATES*4)            // 43008 : 2 x [8][128] h double buffer
#define OFF_XA  (OFF_HH + 2*BPB*HID)        // 45056 : [2 src][2 q][8 b][256 gp*128+j]
#define OFF_XB  (OFF_XA + 2*2*8*256)        // 53248 : [4 q][8 b][128 j]
#define OFF_XS  (OFF_XB + 4*8*128)          // 57344 : [2][64] staged x
#define PH_SMEM_BYTES ((OFF_XS + 128)*4)    // 229888

// GEMM smem
#define G_OFF_WS 0                          // 32 g x 128 c x 4 floats
#define G_OFF_HS (NG*128*4)                 // 16384 : 2 x 1024-float h tile
#define G_SMEM_BYTES ((G_OFF_HS + 2*1024)*4)  // 73728

// ---------------- global scratch (static) ----------------
__device__ __align__(16) float g_P1[NG * GATES * 4];   // packed w_hh0
__device__ __align__(16) float g_P2[NG * GATES * 4];   // packed w_hh1
__device__ __align__(16) float g_P3[NG * GATES * 4];   // packed w_ih1
__device__ __align__(16) float g_h1 [(size_t)NBLK * S_LEN * BPB * HID];    // 268MB
__device__ __align__(16) float g_xg1[(size_t)NBLK * S_LEN * GATES * BPB];  // 1GB

// ---------------- helpers ----------------
typedef unsigned long long u64;
__device__ __forceinline__ void ffma2(u64 &d, u64 a, u64 b) {
    asm("fma.rn.f32x2 %0, %1, %2, %0;" : "+l"(d) : "l"(a), "l"(b));
}
__device__ __forceinline__ float flo(u64 v) { return __uint_as_float((unsigned)v); }
__device__ __forceinline__ float fhi(u64 v) { return __uint_as_float((unsigned)(v >> 32)); }
__device__ __forceinline__ float sigf(float x) {
    return __fdividef(1.0f, 1.0f + __expf(-x));
}
__device__ __forceinline__ float tanhf_fast(float x) {
    float e = __expf(2.0f * x);
    return 1.0f - __fdividef(2.0f, e + 1.0f);
}

// ---------------- K1: pack weights ----------------
__global__ void pack_kernel(const float* __restrict__ whh0,
                            const float* __restrict__ whh1,
                            const float* __restrict__ wih1) {
    int i = blockIdx.x * blockDim.x + threadIdx.x;
    if (i >= GATES * HID) return;
    int col = i / HID, k = i % HID;
    int g = k >> 2, dk = k & 3;
    size_t o = ((size_t)g * GATES + col) * 4 + dk;
    g_P1[o] = whh0[col * HID + k];
    g_P2[o] = whh1[col * HID + k];
    g_P3[o] = wih1[col * HID + k];
}

// ---------------- K3: xg1 = h1 @ w_ih1^T + b_ih1 + b_hh1 ----------------
// grid (4 colslices, NBLK, 2 t-halves), 128 threads, 3 blocks/SM.
// thread: cp = tid>>1 (2 cols), bh = tid&1 (4 batch rows)
__global__ void __launch_bounds__(128, 3) xg1_gemm(const float* __restrict__ bih1,
                                                   const float* __restrict__ bhh1) {
    extern __shared__ float sm[];
    const int tid = threadIdx.x;
    const int cs = blockIdx.x, blk = blockIdx.y;
    const int t0 = blockIdx.z * (S_LEN / 2);
    const int cp = tid >> 1, bh = tid & 1;
    const int col0 = cs * 128 + cp * 2;

    // load weight slice: 32 g x 128 c float4
    {
        const float4* src = (const float4*)g_P3;
        float4*       dst = (float4*)(sm + G_OFF_WS);
        for (int i = tid; i < NG * 128; i += 128) {
            int g = i >> 7, c = i & 127;
            dst[i] = __ldg(&src[g * GATES + cs * 128 + c]);
        }
    }
    float b0 = __ldg(bih1 + col0)     + __ldg(bhh1 + col0);
    float b1 = __ldg(bih1 + col0 + 1) + __ldg(bhh1 + col0 + 1);

    // preload h tile t0
    {
        const float4* hsrc = (const float4*)(g_h1 + ((size_t)blk * S_LEN + t0) * (BPB * HID));
        ((float4*)(sm + G_OFF_HS))[tid * 2]     = __ldg(hsrc + tid * 2);
        ((float4*)(sm + G_OFF_HS))[tid * 2 + 1] = __ldg(hsrc + tid * 2 + 1);
    }
    __syncthreads();

    const ulonglong2* WsD = (const ulonglong2*)(sm + G_OFF_WS);
    int pb = 0;
    for (int tt = 0; tt < S_LEN / 2; tt++) {
        int t = t0 + tt;
        bool has = (tt + 1 < S_LEN / 2);
        float4 pre0, pre1;
        if (has) {
            const float4* hsrc = (const float4*)(g_h1 + ((size_t)blk * S_LEN + t + 1) * (BPB * HID));
            pre0 = __ldg(hsrc + tid * 2);
            pre1 = __ldg(hsrc + tid * 2 + 1);
        }

        const ulonglong2* HtD = (const ulonglong2*)(sm + G_OFF_HS + pb * 1024);
        u64 a0[4] = {0ull,0ull,0ull,0ull}, a1[4] = {0ull,0ull,0ull,0ull};
#pragma unroll 8
        for (int g = 0; g < NG; g++) {
            ulonglong2 w0 = WsD[g * 128 + cp * 2];
            ulonglong2 w1 = WsD[g * 128 + cp * 2 + 1];
#pragma unroll
            for (int r = 0; r < 4; r++) {
                ulonglong2 hv = HtD[(bh * 4 + r) * 32 + g];
                ffma2(a0[r], w0.x, hv.x); ffma2(a0[r], w0.y, hv.y);
                ffma2(a1[r], w1.x, hv.x); ffma2(a1[r], w1.y, hv.y);
            }
        }
        float4 o0 = make_float4(flo(a0[0])+fhi(a0[0])+b0, flo(a0[1])+fhi(a0[1])+b0,
                                flo(a0[2])+fhi(a0[2])+b0, flo(a0[3])+fhi(a0[3])+b0);
        float4 o1 = make_float4(flo(a1[0])+fhi(a1[0])+b1, flo(a1[1])+fhi(a1[1])+b1,
                                flo(a1[2])+fhi(a1[2])+b1, flo(a1[3])+fhi(a1[3])+b1);
        size_t base = ((size_t)(blk * S_LEN + t) * GATES + col0) * BPB + bh * 4;
        *(float4*)(g_xg1 + base)       = o0;
        *(float4*)(g_xg1 + base + BPB) = o1;

        if (has) {
            ((float4*)(sm + G_OFF_HS + (pb ^ 1) * 1024))[tid * 2]     = pre0;
            ((float4*)(sm + G_OFF_HS + (pb ^ 1) * 1024))[tid * 2 + 1] = pre1;
        }
        __syncthreads();
        pb ^= 1;
    }
}

// ---------------- K2/K4: recurrent phases ----------------
// 768 threads = 128 j x 2 gp x 3 kh. kh0: groups 0-10 (cached) + gate assembly.
// kh1: groups 11-20 (cached) + partial export. kh2: groups 21-31 (L2 streamed).
// Finalize (nonlinearity + c/h) distributed over threads 0-511: (j, bpair).
template<int PHASE>
__global__ void __launch_bounds__(NTH, 1) lstm_phase(
    const float* __restrict__ x,
    const float* __restrict__ wih0,
    const float* __restrict__ bih,
    const float* __restrict__ bhh,
    const float* __restrict__ fcw,
    const float* __restrict__ fcb,
    float* __restrict__ out)
{
    extern __shared__ float sm[];
    const float* Pg = (PHASE == 1) ? g_P1 : g_P2;

    const int tid = threadIdx.x;
    const int j   = tid & (HID - 1);
    const int gp  = (tid >> 7) & 1;
    const int kh  = tid >> 8;            // 0,1,2
    const int col0 = gp * 256 + j;       // gate 2gp
    const int col1 = col0 + 128;         // gate 2gp+1
    const int blk  = blockIdx.x;
    const int bg0  = blk * BPB;

    // kh0: biases (+ wih0 rows for phase 1)
    float bias0 = 0.f, bias1 = 0.f, wihr[2][DIN];
    if (kh == 0) {
        int r0 = (2 * gp) * HID + j, r1 = r0 + HID;
        bias0 = __ldg(bih + r0) + __ldg(bhh + r0);
        bias1 = __ldg(bih + r1) + __ldg(bhh + r1);
        if (PHASE == 1) {
#pragma unroll
            for (int d = 0; d < DIN; d++) {
                wihr[0][d] = __ldg(wih0 + r0 * DIN + d);
                wihr[1][d] = __ldg(wih0 + r1 * DIN + d);
            }
        }
    }

    // load cached weights; zero h buffers
    {
        const float4* src = (const float4*)Pg;
        float4*       dst = (float4*)(sm + OFF_WC);
        for (int i = tid; i < NCACHE * GATES; i += NTH) dst[i] = __ldg(src + i);
    }
    for (int i = tid; i < 2 * BPB * HID; i += NTH) sm[OFF_HH + i] = 0.f;
    // phase1: stage x for t=0 into XS buf 0
    if (PHASE == 1 && tid < 64) {
        int b = tid >> 3, d = tid & 7;
        if (d < DIN)
            sm[OFF_XS + b * 8 + d] = __ldg(x + ((size_t)(bg0 + b) * S_LEN + 0) * DIN + d);
    }
    __syncthreads();

    const ulonglong2* WcD = (const ulonglong2*)(sm + OFF_WC);
    const ulonglong2* PgD = (const ulonglong2*)Pg;

    float c0 = 0.f, c1 = 0.f;   // finalize c-state (threads 0-511): rows bp, bp+4

    for (int t = 0; t < S_LEN; t++) {
        const int rb = t & 1, wb = rb ^ 1;
        const ulonglong2* HrD = (const ulonglong2*)(sm + OFF_HH + rb * BPB * HID);

        u64 a0[BPB], a1[BPB];
#pragma unroll
        for (int b = 0; b < BPB; b++) { a0[b] = 0ull; a1[b] = 0ull; }

        float4 xq0a, xq0b, xq1a, xq1b;       // phase2 xg prefetch (kh0)
        float  xst = 0.f;                    // phase1 x staging value (kh2 threads 512-575)

        if (kh == 0) {
            if (PHASE == 2) {
                const float* xp = g_xg1 + ((size_t)(blk * S_LEN + t) * GATES) * BPB;
                xq0a = __ldg((const float4*)(xp + col0 * BPB));
                xq0b = __ldg((const float4*)(xp + col0 * BPB + 4));
                xq1a = __ldg((const float4*)(xp + col1 * BPB));
                xq1b = __ldg((const float4*)(xp + col1 * BPB + 4));
            }
            // groups 0..10 (cached)
#pragma unroll
            for (int g = 0; g < 11; g++) {
                ulonglong2 w0 = WcD[g * GATES + col0];
                ulonglong2 w1 = WcD[g * GATES + col1];
#pragma unroll
                for (int b = 0; b < BPB; b++) {
                    ulonglong2 hv = HrD[b * NG + g];
                    ffma2(a0[b], w0.x, hv.x); ffma2(a0[b], w0.y, hv.y);
                    ffma2(a1[b], w1.x, hv.x); ffma2(a1[b], w1.y, hv.y);
                }
            }
        } else if (kh == 1) {
            // groups 11..20 (cached)
#pragma unroll
            for (int g = 11; g < 21; g++) {
                ulonglong2 w0 = WcD[g * GATES + col0];
                ulonglong2 w1 = WcD[g * GATES + col1];
#pragma unroll
                for (int b = 0; b < BPB; b++) {
                    ulonglong2 hv = HrD[b * NG + g];
                    ffma2(a0[b], w0.x, hv.x); ffma2(a0[b], w0.y, hv.y);
                    ffma2(a1[b], w1.x, hv.x); ffma2(a1[b], w1.y, hv.y);
                }
            }
        } else {
            // phase1: kick off x staging load early (threads 512-575)
            if (PHASE == 1 && tid < 576) {
                int st = tid - 512, b = st >> 3, d = st & 7;
                int tn = (t + 1 < S_LEN) ? t + 1 : t;
                if (d < DIN)
                    xst = __ldg(x + ((size_t)(bg0 + b) * S_LEN + tn) * DIN + d);
            }
            // groups 21..31 streamed from L2 (rolling prefetch depth 3)
            ulonglong2 wsa[3], wsb[3];
#pragma unroll
            for (int s = 0; s < 3; s++) {
                wsa[s] = __ldg(&PgD[(21 + s) * GATES + col0]);
                wsb[s] = __ldg(&PgD[(21 + s) * GATES + col1]);
            }
#pragma unroll
            for (int s = 0; s < 11; s++) {
                int g = 21 + s;
                ulonglong2 w0 = wsa[s % 3], w1 = wsb[s % 3];
                if (s + 3 < 11) {
                    wsa[s % 3] = __ldg(&PgD[(g + 3) * GATES + col0]);
                    wsb[s % 3] = __ldg(&PgD[(g + 3) * GATES + col1]);
                }
#pragma unroll
                for (int b = 0; b < BPB; b++) {
                    ulonglong2 hv = HrD[b * NG + g];
                    ffma2(a0[b], w0.x, hv.x); ffma2(a0[b], w0.y, hv.y);
                    ffma2(a1[b], w1.x, hv.x); ffma2(a1[b], w1.y, hv.y);
                }
            }
        }

        // exporters: kh1, kh2 -> XA[src][q][b][gp*128+j]
        if (kh >= 1) {
            float* Xa = sm + OFF_XA + (kh - 1) * 4096 + gp * 128 + j;
#pragma unroll
            for (int b = 0; b < BPB; b++) {
                Xa[0 * 2048 + b * 256] = flo(a0[b]) + fhi(a0[b]);
                Xa[1 * 2048 + b * 256] = flo(a1[b]) + fhi(a1[b]);
            }
        }
        __syncthreads();   // 1

        if (kh == 0) {
            // assemble full gate pre-activations -> XB[q][b][j]
            const float* Xa = sm + OFF_XA + gp * 128 + j;
            float xg0v[BPB], xg1v[BPB];
            if (PHASE == 1) {
                const float* xs = sm + OFF_XS + rb * 64;
#pragma unroll
                for (int b = 0; b < BPB; b++) {
                    float s0 = bias0, s1 = bias1;
#pragma unroll
                    for (int d = 0; d < DIN; d++) {
                        float xv = xs[b * 8 + d];
                        s0 = fmaf(wihr[0][d], xv, s0);
                        s1 = fmaf(wihr[1][d], xv, s1);
                    }
                    xg0v[b] = s0; xg1v[b] = s1;
                }
            } else {
                float q0[8] = {xq0a.x,xq0a.y,xq0a.z,xq0a.w, xq0b.x,xq0b.y,xq0b.z,xq0b.w};
                float q1[8] = {xq1a.x,xq1a.y,xq1a.z,xq1a.w, xq1b.x,xq1b.y,xq1b.z,xq1b.w};
#pragma unroll
                for (int b = 0; b < BPB; b++) { xg0v[b] = q0[b]; xg1v[b] = q1[b]; }
            }
            float* Xb = sm + OFF_XB;
#pragma unroll
            for (int b = 0; b < BPB; b++) {
                float p0 = flo(a0[b]) + fhi(a0[b]) + Xa[0*2048 + b*256] + Xa[4096 + 0*2048 + b*256] + xg0v[b];
                float p1 = flo(a1[b]) + fhi(a1[b]) + Xa[1*2048 + b*256] + Xa[4096 + 1*2048 + b*256] + xg1v[b];
                Xb[(2*gp + 0) * 1024 + b * 128 + j] = p0;
                Xb[(2*gp + 1) * 1024 + b * 128 + j] = p1;
            }
        }
        __syncthreads();   // 2

        // distributed finalize: threads 0-511, (j, bp) -> rows bp, bp+4
        if (tid < 512) {
            const int bp = tid >> 7;
            float* Hw = sm + OFF_HH + wb * BPB * HID;
            const float* Xb = sm + OFF_XB;
#pragma unroll
            for (int r = 0; r < 2; r++) {
                int b = bp + r * 4;
                float iv = Xb[0 * 1024 + b * 128 + j];
                float fv = Xb[1 * 1024 + b * 128 + j];
                float gv = Xb[2 * 1024 + b * 128 + j];
                float ov = Xb[3 * 1024 + b * 128 + j];
                float cc = (r == 0) ? c0 : c1;
                cc = sigf(fv) * cc + sigf(iv) * tanhf_fast(gv);
                if (r == 0) c0 = cc; else c1 = cc;
                float h = sigf(ov) * tanhf_fast(cc);
                Hw[b * HID + j] = h;
                if (PHASE == 1)
                    g_h1[((size_t)(blk * S_LEN + t) * BPB + b) * HID + j] = h;
            }
        } else if (PHASE == 1 && tid < 576) {
            int st = tid - 512, b = st >> 3, d = st & 7;
            if (d < DIN) sm[OFF_XS + wb * 64 + b * 8 + d] = xst;
        }
        __syncthreads();   // 3
    }

    if (PHASE == 2) {
        const float* hfin = sm + OFF_HH;   // t=511 wrote buffer 0
        int w = tid >> 5, lane = tid & 31;
        if (w < BPB) {
            float s = 0.f;
#pragma unroll
            for (int m = 0; m < HID; m += 32)
                s += hfin[w * HID + lane + m] * __ldg(fcw + lane + m);
#pragma unroll
            for (int o = 16; o > 0; o >>= 1) s += __shfl_down_sync(0xffffffffu, s, o);
            if (lane == 0) out[bg0 + w] = s + __ldg(fcb);
        }
    }
}

// ---------------- launch ----------------
extern "C" void kernel_launch(void* const* d_in, const int* in_sizes, int n_in,
                              void* d_out, int out_size) {
    const float* x    = (const float*)d_in[0];
    const float* wih0 = (const float*)d_in[1];
    const float* whh0 = (const float*)d_in[2];
    const float* bih0 = (const float*)d_in[3];
    const float* bhh0 = (const float*)d_in[4];
    const float* wih1 = (const float*)d_in[5];
    const float* whh1 = (const float*)d_in[6];
    const float* bih1 = (const float*)d_in[7];
    const float* bhh1 = (const float*)d_in[8];
    const float* fcw  = (const float*)d_in[9];
    const float* fcb  = (const float*)d_in[10];
    float* out = (float*)d_out;
    (void)in_sizes; (void)n_in; (void)out_size;

    cudaFuncSetAttribute(lstm_phase<1>, cudaFuncAttributeMaxDynamicSharedMemorySize, PH_SMEM_BYTES);
    cudaFuncSetAttribute(lstm_phase<2>, cudaFuncAttributeMaxDynamicSharedMemorySize, PH_SMEM_BYTES);
    cudaFuncSetAttribute(xg1_gemm,      cudaFuncAttributeMaxDynamicSharedMemorySize, G_SMEM_BYTES);

    pack_kernel<<<(GATES * HID + 255) / 256, 256>>>(whh0, whh1, wih1);
    lstm_phase<1><<<NBLK, NTH, PH_SMEM_BYTES>>>(x, wih0, bih0, bhh0, fcw, fcb, out);
    xg1_gemm<<<dim3(4, NBLK, 2), 128, G_SMEM_BYTES>>>(bih1, bhh1);
    lstm_phase<2><<<NBLK, NTH, PH_SMEM_BYTES>>>(x, wih0, bih1, bhh1, fcw, fcb, out);
}